// round 1
// baseline (speedup 1.0000x reference)
#include <cuda_runtime.h>
#include <cuda_bf16.h>
#include <cstddef>

// Problem constants
#define V_SZ   100000
#define D_SZ   256
#define S_SZ   128
#define H_SZ   512
#define B_SZ   8192
#define K_SZ   32
#define NREG   60000
#define RARE   (V_SZ - NREG)   // 40000

// Scratch (device globals; no allocation allowed)
__device__ float g_hidden[RARE * H_SZ];   // reused for t-MLP hidden (8192x512 fits)
__device__ float g_cm[RARE * D_SZ];       // c-MLP table for rare vocab
__device__ float g_tu[B_SZ * D_SZ];       // t-MLP for every pos_u row
__device__ float g_partial[B_SZ / 8];     // block partial sums (1024)

// ---------------------------------------------------------------------------
// Generic fp32 GEMM: C[M,N] = act( gatherA[M,K] @ W[K,N] + bias[N] )
// A row m comes from A + row*lda where row = row_idx ? row_idx[m] : row_off+m.
// BM=128, BN=64, BK=32, 256 threads, 8x4 per thread.
// ---------------------------------------------------------------------------
#define BM 128
#define BN 64
#define BK 32
#define TM 8
#define TN 4

__global__ __launch_bounds__(256) void gemm_kernel(
    const float* __restrict__ A, const int* __restrict__ row_idx, int row_off, int lda,
    const float* __restrict__ W, const float* __restrict__ bias,
    float* __restrict__ C, int M, int N, int Kdim, int do_relu)
{
    __shared__ float As[BK][BM + 1];   // [k][m], padded: conflict-free transposed stores
    __shared__ float Bs[BK][BN + 4];   // row stride 68 floats = 272B (16B aligned)

    const int tid = threadIdx.x;
    const int ty = tid >> 4;           // 0..15 -> row group
    const int tx = tid & 15;           // 0..15 -> col group
    const int m0 = blockIdx.x * BM;
    const int n0 = blockIdx.y * BN;

    // A-load mapping: 32 rows per pass, 8 float4 per row
    const int arow = tid >> 3;         // 0..31
    const int ak   = (tid & 7) * 4;    // 0,4,...,28
    // B-load mapping: 16 k-rows per pass, 16 float4 per row
    const int bk = tid >> 4;           // 0..15
    const int bn = (tid & 15) * 4;

    float acc[TM][TN];
    #pragma unroll
    for (int i = 0; i < TM; i++)
        #pragma unroll
        for (int j = 0; j < TN; j++) acc[i][j] = 0.f;

    for (int k0 = 0; k0 < Kdim; k0 += BK) {
        // Load A tile (transposed into SMEM)
        #pragma unroll
        for (int p = 0; p < 4; p++) {
            int m  = m0 + p * 32 + arow;
            int mm = m < M ? m : M - 1;                 // clamp OOB rows (stores are guarded)
            int r  = row_idx ? row_idx[mm] : (row_off + mm);
            const float4 v = *(const float4*)(A + (size_t)r * lda + k0 + ak);
            As[ak + 0][p * 32 + arow] = v.x;
            As[ak + 1][p * 32 + arow] = v.y;
            As[ak + 2][p * 32 + arow] = v.z;
            As[ak + 3][p * 32 + arow] = v.w;
        }
        // Load B tile
        #pragma unroll
        for (int p = 0; p < 2; p++) {
            int k = k0 + p * 16 + bk;
            *(float4*)&Bs[p * 16 + bk][bn] = *(const float4*)(W + (size_t)k * N + n0 + bn);
        }
        __syncthreads();

        #pragma unroll
        for (int kk = 0; kk < BK; kk++) {
            float a[TM], b[TN];
            #pragma unroll
            for (int i = 0; i < TM; i++) a[i] = As[kk][ty * TM + i];
            float4 bv = *(const float4*)&Bs[kk][tx * TN];
            b[0] = bv.x; b[1] = bv.y; b[2] = bv.z; b[3] = bv.w;
            #pragma unroll
            for (int i = 0; i < TM; i++)
                #pragma unroll
                for (int j = 0; j < TN; j++)
                    acc[i][j] = fmaf(a[i], b[j], acc[i][j]);
        }
        __syncthreads();
    }

    // Epilogue: bias (+ optional relu), guarded float4 stores
    #pragma unroll
    for (int i = 0; i < TM; i++) {
        int m = m0 + ty * TM + i;
        if (m >= M) continue;
        int n = n0 + tx * TN;
        float4 c;
        c.x = acc[i][0] + bias[n + 0];
        c.y = acc[i][1] + bias[n + 1];
        c.z = acc[i][2] + bias[n + 2];
        c.w = acc[i][3] + bias[n + 3];
        if (do_relu) {
            c.x = fmaxf(c.x, 0.f); c.y = fmaxf(c.y, 0.f);
            c.z = fmaxf(c.z, 0.f); c.w = fmaxf(c.w, 0.f);
        }
        *(float4*)(C + (size_t)m * N + n) = c;
    }
}

// ---------------------------------------------------------------------------
// Scoring: one warp per pair b.
// total_b = 2*( -logsig(clip(EU.EV)) + sum_k -logsig(-clip(EU.ENVk)) )
// ---------------------------------------------------------------------------
__device__ __forceinline__ float clip10(float x) {
    return fminf(fmaxf(x, -10.f), 10.f);
}

__device__ __forceinline__ float warp_reduce(float v) {
    #pragma unroll
    for (int s = 16; s > 0; s >>= 1) v += __shfl_xor_sync(0xffffffffu, v, s);
    return v;
}

__global__ __launch_bounds__(256) void score_kernel(
    const int* __restrict__ pos_u, const int* __restrict__ pos_v,
    const int* __restrict__ neg_v,
    const float* __restrict__ u_emb, const float* __restrict__ v_emb)
{
    __shared__ float bsum[8];
    const int warp = threadIdx.x >> 5;
    const int lane = threadIdx.x & 31;
    const int b = blockIdx.x * 8 + warp;

    const int pu = pos_u[b];
    const int pv = pos_v[b];

    const float4* eup = (const float4*)(pu < NREG ? u_emb + (size_t)pu * D_SZ
                                                  : g_tu + (size_t)b * D_SZ);
    const float4* evp = (const float4*)(pv < NREG ? v_emb + (size_t)pv * D_SZ
                                                  : g_cm + (size_t)(pv - NREG) * D_SZ);

    const float4 e0 = eup[lane * 2 + 0];
    const float4 e1 = eup[lane * 2 + 1];
    const float4 v0 = evp[lane * 2 + 0];
    const float4 v1 = evp[lane * 2 + 1];

    float d = e0.x * v0.x + e0.y * v0.y + e0.z * v0.z + e0.w * v0.w
            + e1.x * v1.x + e1.y * v1.y + e1.z * v1.z + e1.w * v1.w;
    d = warp_reduce(d);
    float x = clip10(d);
    // -logsig(x) = log1p(exp(-|x|)) - min(x,0)
    float s = log1pf(expf(-fabsf(x))) - fminf(x, 0.f);

    const int mynv = neg_v[(size_t)b * K_SZ + lane];
    #pragma unroll 4
    for (int k = 0; k < K_SZ; k++) {
        int nv = __shfl_sync(0xffffffffu, mynv, k);
        const float4* np = (const float4*)(nv < NREG ? v_emb + (size_t)nv * D_SZ
                                                     : g_cm + (size_t)(nv - NREG) * D_SZ);
        float4 n0 = np[lane * 2 + 0];
        float4 n1 = np[lane * 2 + 1];
        float dn = e0.x * n0.x + e0.y * n0.y + e0.z * n0.z + e0.w * n0.w
                 + e1.x * n1.x + e1.y * n1.y + e1.z * n1.z + e1.w * n1.w;
        dn = warp_reduce(dn);
        float xn = clip10(dn);
        // -logsig(-x) = max(x,0) + log1p(exp(-|x|))
        s += fmaxf(xn, 0.f) + log1pf(expf(-fabsf(xn)));
    }

    if (lane == 0) bsum[warp] = 2.f * s;
    __syncthreads();
    if (threadIdx.x == 0) {
        float t = 0.f;
        #pragma unroll
        for (int i = 0; i < 8; i++) t += bsum[i];
        g_partial[blockIdx.x] = t;
    }
}

__global__ __launch_bounds__(1024) void reduce_kernel(float* __restrict__ out) {
    __shared__ float s[1024];
    const int t = threadIdx.x;
    s[t] = g_partial[t];
    __syncthreads();
    #pragma unroll
    for (int st = 512; st > 0; st >>= 1) {
        if (t < st) s[t] += s[t + st];
        __syncthreads();
    }
    if (t == 0) out[0] = s[0] / (float)B_SZ;
}

// ---------------------------------------------------------------------------
// Launch
// ---------------------------------------------------------------------------
extern "C" void kernel_launch(void* const* d_in, const int* in_sizes, int n_in,
                              void* d_out, int out_size)
{
    const int*   pos_u  = (const int*)  d_in[0];
    const int*   pos_v  = (const int*)  d_in[1];
    const int*   neg_v  = (const int*)  d_in[2];
    const float* u_emb  = (const float*)d_in[3];
    const float* v_emb  = (const float*)d_in[4];
    const float* stoich = (const float*)d_in[5];
    const float* tw1    = (const float*)d_in[6];
    const float* tb1    = (const float*)d_in[7];
    const float* tw2    = (const float*)d_in[8];
    const float* tb2    = (const float*)d_in[9];
    const float* cw1    = (const float*)d_in[10];
    const float* cb1    = (const float*)d_in[11];
    const float* cw2    = (const float*)d_in[12];
    const float* cb2    = (const float*)d_in[13];
    float* out = (float*)d_out;

    float* hidden; float* cm; float* tu;
    cudaGetSymbolAddress((void**)&hidden, g_hidden);
    cudaGetSymbolAddress((void**)&cm, g_cm);
    cudaGetSymbolAddress((void**)&tu, g_tu);

    // 1) c-MLP layer1 over all rare vocab: hidden = relu(stoich[60000+i] @ cw1 + cb1)
    {
        dim3 grid((RARE + BM - 1) / BM, H_SZ / BN);
        gemm_kernel<<<grid, 256>>>(stoich, nullptr, NREG, S_SZ,
                                   cw1, cb1, hidden, RARE, H_SZ, S_SZ, 1);
    }
    // 2) c-MLP layer2: g_cm = hidden @ cw2 + cb2
    {
        dim3 grid((RARE + BM - 1) / BM, D_SZ / BN);
        gemm_kernel<<<grid, 256>>>(hidden, nullptr, 0, H_SZ,
                                   cw2, cb2, cm, RARE, D_SZ, H_SZ, 0);
    }
    // 3) t-MLP layer1 on gathered pos_u rows (reuses hidden buffer)
    {
        dim3 grid(B_SZ / BM, H_SZ / BN);
        gemm_kernel<<<grid, 256>>>(stoich, pos_u, 0, S_SZ,
                                   tw1, tb1, hidden, B_SZ, H_SZ, S_SZ, 1);
    }
    // 4) t-MLP layer2: g_tu = hidden @ tw2 + tb2
    {
        dim3 grid(B_SZ / BM, D_SZ / BN);
        gemm_kernel<<<grid, 256>>>(hidden, nullptr, 0, H_SZ,
                                   tw2, tb2, tu, B_SZ, D_SZ, H_SZ, 0);
    }
    // 5) scoring: one warp per pair, 8 pairs per block -> 1024 blocks
    score_kernel<<<B_SZ / 8, 256>>>(pos_u, pos_v, neg_v, u_emb, v_emb);
    // 6) final deterministic reduction + mean
    reduce_kernel<<<1, 1024>>>(out);

    (void)in_sizes; (void)n_in; (void)out_size;
}

// round 3
// speedup vs baseline: 3.3972x; 3.3972x over previous
#include <cuda_runtime.h>
#include <cuda_bf16.h>
#include <cstdint>
#include <cstddef>

// Problem constants
#define V_SZ   100000
#define D_SZ   256
#define S_SZ   128
#define H_SZ   512
#define B_SZ   8192
#define K_SZ   32
#define NREG   60000
#define RARE   40000

// ---------------------------------------------------------------------------
// Scratch (device globals; allocation is forbidden)
// ---------------------------------------------------------------------------
__device__ __nv_bfloat16 g_srare[RARE * S_SZ];        // rare stoich rows, bf16
__device__ __nv_bfloat16 g_sposu[B_SZ * S_SZ];        // gathered pos_u stoich, bf16
__device__ __nv_bfloat16 g_cw1t[H_SZ * S_SZ];         // cw1^T [512x128] (n-major, k contig)
__device__ __nv_bfloat16 g_cw2t[D_SZ * H_SZ];         // cw2^T [256x512]
__device__ __nv_bfloat16 g_tw1t[H_SZ * S_SZ];         // tw1^T
__device__ __nv_bfloat16 g_tw2t[D_SZ * H_SZ];         // tw2^T
__device__ float g_cm[RARE * D_SZ];                   // c-MLP table (rare vocab)
__device__ float g_tu[B_SZ * D_SZ];                   // t-MLP per pos_u row
__device__ float g_partial[B_SZ / 8];

// ---------------------------------------------------------------------------
// Warp MMA helpers (base sm_103-legal: ldmatrix + mma.sync HMMA)
// ---------------------------------------------------------------------------
__device__ __forceinline__ uint32_t smem_u32(const void* p) {
    uint32_t a;
    asm("{ .reg .u64 t; cvta.to.shared.u64 t, %1; cvt.u32.u64 %0, t; }" : "=r"(a) : "l"(p));
    return a;
}

__device__ __forceinline__ void ldsm4(uint32_t& r0, uint32_t& r1, uint32_t& r2, uint32_t& r3,
                                      uint32_t addr) {
    asm volatile("ldmatrix.sync.aligned.m8n8.x4.shared.b16 {%0,%1,%2,%3}, [%4];"
                 : "=r"(r0), "=r"(r1), "=r"(r2), "=r"(r3) : "r"(addr));
}

__device__ __forceinline__ void mma16816(float* c, const uint32_t* a, const uint32_t* b) {
    asm volatile(
        "mma.sync.aligned.m16n8k16.row.col.f32.bf16.bf16.f32 "
        "{%0,%1,%2,%3}, {%4,%5,%6,%7}, {%8,%9}, {%0,%1,%2,%3};"
        : "+f"(c[0]), "+f"(c[1]), "+f"(c[2]), "+f"(c[3])
        : "r"(a[0]), "r"(a[1]), "r"(a[2]), "r"(a[3]), "r"(b[0]), "r"(b[1]));
}

// SMEM layout (bytes, dynamic)
#define SM_A 0              // 128x128 bf16, 256B rows, XOR-swizzled (32KB)
#define SM_W 32768          // 128x128 bf16 W chunk (32KB)
#define SM_H 65536          // 128x512 bf16 hidden, 1024B rows (128KB)
#define SM_TOTAL 196608

// ---------------------------------------------------------------------------
// Fused 2-layer MLP: C[M,256] = relu(A[M,128] @ W1 + b1) @ W2 + b2
// A bf16 row-major (pre-gathered); W1t [512x128], W2t [256x512] bf16 K-major.
// 256 threads = 8 warps (4 M-warps x 2 N-warps); 128 rows per CTA.
// ---------------------------------------------------------------------------
__global__ __launch_bounds__(256) void mlp_kernel(
    const __nv_bfloat16* __restrict__ A,
    const __nv_bfloat16* __restrict__ W1t, const float* __restrict__ b1,
    const __nv_bfloat16* __restrict__ W2t, const float* __restrict__ b2,
    float* __restrict__ C, int M)
{
    extern __shared__ char smem[];
    const uint32_t sb = smem_u32(smem);
    const int tid = threadIdx.x;
    const int lane = tid & 31;
    const int wid = tid >> 5;
    const int mw = wid & 3;              // M-warp: stripe of 32 rows
    const int nw = wid >> 2;             // N-warp: 64-col half of a 128-col chunk
    const int m0 = blockIdx.x * 128;

    // ---- Load A tile (128 rows x 128 bf16) into swizzled SMEM ----
    #pragma unroll
    for (int i = 0; i < 8; i++) {
        int c = i * 256 + tid;           // chunk id: 2048 chunks of 16B
        int row = c >> 4, ch = c & 15;
        int rg = m0 + row; if (rg > M - 1) rg = M - 1;
        uint4 v = ((const uint4*)A)[(size_t)rg * 16 + ch];
        *(uint4*)(smem + SM_A + row * 256 + ((ch ^ (row & 7)) << 4)) = v;
    }

    float acc[2][8][4];

    // =================== Layer 1: hidden[128,512], 4 N-chunks ===================
    for (int cch = 0; cch < 4; cch++) {
        __syncthreads();                 // Wbuf free (prev chunk's mma done)
        #pragma unroll
        for (int i = 0; i < 8; i++) {
            int c = i * 256 + tid;
            int r = c >> 4, ch = c & 15;
            uint4 v = ((const uint4*)W1t)[(size_t)(cch * 128 + r) * 16 + ch];
            *(uint4*)(smem + SM_W + r * 256 + ((ch ^ (r & 7)) << 4)) = v;
        }
        __syncthreads();

        #pragma unroll
        for (int mt = 0; mt < 2; mt++)
            #pragma unroll
            for (int nt = 0; nt < 8; nt++)
                #pragma unroll
                for (int q = 0; q < 4; q++) acc[mt][nt][q] = 0.f;

        #pragma unroll
        for (int ks = 0; ks < 8; ks++) {
            uint32_t a[2][4];
            #pragma unroll
            for (int mt = 0; mt < 2; mt++) {
                int row = mw * 32 + mt * 16 + (lane & 15);
                int ch  = ks * 2 + (lane >> 4);
                ldsm4(a[mt][0], a[mt][1], a[mt][2], a[mt][3],
                      sb + SM_A + row * 256 + ((ch ^ (row & 7)) << 4));
            }
            uint32_t b[8][2];
            #pragma unroll
            for (int ntp = 0; ntp < 4; ntp++) {
                int row = nw * 64 + ntp * 16 + (lane & 7) + ((lane >> 4) << 3);
                int ch  = ks * 2 + ((lane >> 3) & 1);
                ldsm4(b[2 * ntp][0], b[2 * ntp][1], b[2 * ntp + 1][0], b[2 * ntp + 1][1],
                      sb + SM_W + row * 256 + ((ch ^ (row & 7)) << 4));
            }
            #pragma unroll
            for (int mt = 0; mt < 2; mt++)
                #pragma unroll
                for (int nt = 0; nt < 8; nt++)
                    mma16816(acc[mt][nt], a[mt], b[nt]);
        }

        // Epilogue: bias + relu -> bf16 hidden in SMEM (own warp's rows only)
        #pragma unroll
        for (int mt = 0; mt < 2; mt++)
            #pragma unroll
            for (int nt = 0; nt < 8; nt++) {
                int nloc = nw * 64 + nt * 8 + 2 * (lane & 3);
                int ng = cch * 128 + nloc;              // hidden col 0..511
                float2 bb = *(const float2*)(b1 + ng);
                float h0 = fmaxf(acc[mt][nt][0] + bb.x, 0.f);
                float h1 = fmaxf(acc[mt][nt][1] + bb.y, 0.f);
                float h2 = fmaxf(acc[mt][nt][2] + bb.x, 0.f);
                float h3 = fmaxf(acc[mt][nt][3] + bb.y, 0.f);
                __nv_bfloat162 p0 = __float22bfloat162_rn(make_float2(h0, h1));
                __nv_bfloat162 p1 = __float22bfloat162_rn(make_float2(h2, h3));
                int ch = ng >> 3, w = (ng & 7) * 2;
                int r0 = mw * 32 + mt * 16 + (lane >> 2);
                int r1 = r0 + 8;
                *(unsigned*)(smem + SM_H + r0 * 1024 + ((ch ^ (r0 & 7)) << 4) + w) =
                    *(unsigned*)&p0;
                *(unsigned*)(smem + SM_H + r1 * 1024 + ((ch ^ (r1 & 7)) << 4) + w) =
                    *(unsigned*)&p1;
            }
    }

    // =================== Layer 2: out[128,256] = hidden @ W2 ===================
    for (int nc = 0; nc < 2; nc++) {
        #pragma unroll
        for (int mt = 0; mt < 2; mt++)
            #pragma unroll
            for (int nt = 0; nt < 8; nt++)
                #pragma unroll
                for (int q = 0; q < 4; q++) acc[mt][nt][q] = 0.f;

        for (int kc = 0; kc < 4; kc++) {
            __syncthreads();
            #pragma unroll
            for (int i = 0; i < 8; i++) {
                int c = i * 256 + tid;
                int r = c >> 4, ch = c & 15;
                uint4 v = ((const uint4*)W2t)[(size_t)(nc * 128 + r) * 64 + kc * 16 + ch];
                *(uint4*)(smem + SM_W + r * 256 + ((ch ^ (r & 7)) << 4)) = v;
            }
            __syncthreads();

            #pragma unroll
            for (int ks = 0; ks < 8; ks++) {
                uint32_t a[2][4];
                #pragma unroll
                for (int mt = 0; mt < 2; mt++) {
                    int row = mw * 32 + mt * 16 + (lane & 15);
                    int ch  = kc * 16 + ks * 2 + (lane >> 4);
                    ldsm4(a[mt][0], a[mt][1], a[mt][2], a[mt][3],
                          sb + SM_H + row * 1024 + ((ch ^ (row & 7)) << 4));
                }
                uint32_t b[8][2];
                #pragma unroll
                for (int ntp = 0; ntp < 4; ntp++) {
                    int row = nw * 64 + ntp * 16 + (lane & 7) + ((lane >> 4) << 3);
                    int ch  = ks * 2 + ((lane >> 3) & 1);
                    ldsm4(b[2 * ntp][0], b[2 * ntp][1], b[2 * ntp + 1][0], b[2 * ntp + 1][1],
                          sb + SM_W + row * 256 + ((ch ^ (row & 7)) << 4));
                }
                #pragma unroll
                for (int mt = 0; mt < 2; mt++)
                    #pragma unroll
                    for (int nt = 0; nt < 8; nt++)
                        mma16816(acc[mt][nt], a[mt], b[nt]);
            }
        }

        // Epilogue: + bias -> fp32 global
        #pragma unroll
        for (int mt = 0; mt < 2; mt++)
            #pragma unroll
            for (int nt = 0; nt < 8; nt++) {
                int ng = nc * 128 + nw * 64 + nt * 8 + 2 * (lane & 3);
                float2 bb = *(const float2*)(b2 + ng);
                int r0 = m0 + mw * 32 + mt * 16 + (lane >> 2);
                int r1 = r0 + 8;
                if (r0 < M) {
                    float2 o = make_float2(acc[mt][nt][0] + bb.x, acc[mt][nt][1] + bb.y);
                    *(float2*)(C + (size_t)r0 * D_SZ + ng) = o;
                }
                if (r1 < M) {
                    float2 o = make_float2(acc[mt][nt][2] + bb.x, acc[mt][nt][3] + bb.y);
                    *(float2*)(C + (size_t)r1 * D_SZ + ng) = o;
                }
            }
    }
}

// ---------------------------------------------------------------------------
// Prep kernels
// ---------------------------------------------------------------------------
__global__ __launch_bounds__(256) void conv_rare_kernel(const float* __restrict__ stoich) {
    int t = blockIdx.x * blockDim.x + threadIdx.x;   // per float4
    if (t >= RARE * S_SZ / 4) return;
    float4 f = ((const float4*)(stoich + (size_t)NREG * S_SZ))[t];
    __nv_bfloat162 h0 = __float22bfloat162_rn(make_float2(f.x, f.y));
    __nv_bfloat162 h1 = __float22bfloat162_rn(make_float2(f.z, f.w));
    uint2 u; u.x = *(unsigned*)&h0; u.y = *(unsigned*)&h1;
    ((uint2*)g_srare)[t] = u;
}

__global__ __launch_bounds__(256) void gather_posu_kernel(
    const float* __restrict__ stoich, const int* __restrict__ pos_u) {
    int t = blockIdx.x * blockDim.x + threadIdx.x;   // B_SZ*32
    int row = t >> 5, c4 = t & 31;
    int r = pos_u[row];
    float4 f = ((const float4*)(stoich + (size_t)r * S_SZ))[c4];
    __nv_bfloat162 h0 = __float22bfloat162_rn(make_float2(f.x, f.y));
    __nv_bfloat162 h1 = __float22bfloat162_rn(make_float2(f.z, f.w));
    uint2 u; u.x = *(unsigned*)&h0; u.y = *(unsigned*)&h1;
    ((uint2*)g_sposu)[(size_t)row * 32 + c4] = u;
}

__global__ __launch_bounds__(256) void transpose_w_kernel(
    const float* __restrict__ w, __nv_bfloat16* __restrict__ wt, int K, int N) {
    // w [K x N] -> wt [N x K] (K-major rows)
    int t = blockIdx.x * blockDim.x + threadIdx.x;
    if (t >= K * N) return;
    int n = t / K, k = t % K;
    wt[t] = __float2bfloat16(w[(size_t)k * N + n]);
}

// ---------------------------------------------------------------------------
// Scoring (fp32): one warp per pair.
// total_b = 2*( -logsig(clip(EU.EV)) + sum_k -logsig(-clip(EU.ENVk)) )
// ---------------------------------------------------------------------------
__device__ __forceinline__ float clip10(float x) { return fminf(fmaxf(x, -10.f), 10.f); }
__device__ __forceinline__ float warp_reduce(float v) {
    #pragma unroll
    for (int s = 16; s > 0; s >>= 1) v += __shfl_xor_sync(0xffffffffu, v, s);
    return v;
}

__global__ __launch_bounds__(256) void score_kernel(
    const int* __restrict__ pos_u, const int* __restrict__ pos_v,
    const int* __restrict__ neg_v,
    const float* __restrict__ u_emb, const float* __restrict__ v_emb)
{
    __shared__ float bsum[8];
    const int warp = threadIdx.x >> 5;
    const int lane = threadIdx.x & 31;
    const int b = blockIdx.x * 8 + warp;

    const int pu = pos_u[b];
    const int pv = pos_v[b];

    const float4* eup = (const float4*)(pu < NREG ? u_emb + (size_t)pu * D_SZ
                                                  : g_tu + (size_t)b * D_SZ);
    const float4* evp = (const float4*)(pv < NREG ? v_emb + (size_t)pv * D_SZ
                                                  : g_cm + (size_t)(pv - NREG) * D_SZ);
    const float4 e0 = eup[lane * 2 + 0];
    const float4 e1 = eup[lane * 2 + 1];
    const float4 v0 = evp[lane * 2 + 0];
    const float4 v1 = evp[lane * 2 + 1];

    float d = e0.x * v0.x + e0.y * v0.y + e0.z * v0.z + e0.w * v0.w
            + e1.x * v1.x + e1.y * v1.y + e1.z * v1.z + e1.w * v1.w;
    d = warp_reduce(d);
    float x = clip10(d);
    float s = log1pf(expf(-fabsf(x))) - fminf(x, 0.f);

    const int mynv = neg_v[(size_t)b * K_SZ + lane];
    #pragma unroll 4
    for (int k = 0; k < K_SZ; k++) {
        int nv = __shfl_sync(0xffffffffu, mynv, k);
        const float4* np = (const float4*)(nv < NREG ? v_emb + (size_t)nv * D_SZ
                                                     : g_cm + (size_t)(nv - NREG) * D_SZ);
        float4 n0 = np[lane * 2 + 0];
        float4 n1 = np[lane * 2 + 1];
        float dn = e0.x * n0.x + e0.y * n0.y + e0.z * n0.z + e0.w * n0.w
                 + e1.x * n1.x + e1.y * n1.y + e1.z * n1.z + e1.w * n1.w;
        dn = warp_reduce(dn);
        float xn = clip10(dn);
        s += fmaxf(xn, 0.f) + log1pf(expf(-fabsf(xn)));
    }

    if (lane == 0) bsum[warp] = 2.f * s;
    __syncthreads();
    if (threadIdx.x == 0) {
        float t = 0.f;
        #pragma unroll
        for (int i = 0; i < 8; i++) t += bsum[i];
        g_partial[blockIdx.x] = t;
    }
}

__global__ __launch_bounds__(1024) void reduce_kernel(float* __restrict__ out) {
    __shared__ float s[1024];
    const int t = threadIdx.x;
    s[t] = g_partial[t];
    __syncthreads();
    #pragma unroll
    for (int st = 512; st > 0; st >>= 1) {
        if (t < st) s[t] += s[t + st];
        __syncthreads();
    }
    if (t == 0) out[0] = s[0] / (float)B_SZ;
}

// ---------------------------------------------------------------------------
// Launch
// ---------------------------------------------------------------------------
extern "C" void kernel_launch(void* const* d_in, const int* in_sizes, int n_in,
                              void* d_out, int out_size)
{
    const int*   pos_u  = (const int*)  d_in[0];
    const int*   pos_v  = (const int*)  d_in[1];
    const int*   neg_v  = (const int*)  d_in[2];
    const float* u_emb  = (const float*)d_in[3];
    const float* v_emb  = (const float*)d_in[4];
    const float* stoich = (const float*)d_in[5];
    const float* tw1    = (const float*)d_in[6];
    const float* tb1    = (const float*)d_in[7];
    const float* tw2    = (const float*)d_in[8];
    const float* tb2    = (const float*)d_in[9];
    const float* cw1    = (const float*)d_in[10];
    const float* cb1    = (const float*)d_in[11];
    const float* cw2    = (const float*)d_in[12];
    const float* cb2    = (const float*)d_in[13];
    float* out = (float*)d_out;

    __nv_bfloat16 *srare, *sposu, *cw1t, *cw2t, *tw1t, *tw2t;
    float *cm, *tu;
    cudaGetSymbolAddress((void**)&srare, g_srare);
    cudaGetSymbolAddress((void**)&sposu, g_sposu);
    cudaGetSymbolAddress((void**)&cw1t, g_cw1t);
    cudaGetSymbolAddress((void**)&cw2t, g_cw2t);
    cudaGetSymbolAddress((void**)&tw1t, g_tw1t);
    cudaGetSymbolAddress((void**)&tw2t, g_tw2t);
    cudaGetSymbolAddress((void**)&cm, g_cm);
    cudaGetSymbolAddress((void**)&tu, g_tu);

    cudaFuncSetAttribute(mlp_kernel, cudaFuncAttributeMaxDynamicSharedMemorySize, SM_TOTAL);

    // Prep: convert/gather/transpose to bf16
    conv_rare_kernel<<<(RARE * S_SZ / 4 + 255) / 256, 256>>>(stoich);
    gather_posu_kernel<<<(B_SZ * 32 + 255) / 256, 256>>>(stoich, pos_u);
    transpose_w_kernel<<<(S_SZ * H_SZ + 255) / 256, 256>>>(cw1, cw1t, S_SZ, H_SZ);
    transpose_w_kernel<<<(H_SZ * D_SZ + 255) / 256, 256>>>(cw2, cw2t, H_SZ, D_SZ);
    transpose_w_kernel<<<(S_SZ * H_SZ + 255) / 256, 256>>>(tw1, tw1t, S_SZ, H_SZ);
    transpose_w_kernel<<<(H_SZ * D_SZ + 255) / 256, 256>>>(tw2, tw2t, H_SZ, D_SZ);

    // c-MLP over all rare vocab rows -> g_cm  (313 CTAs)
    mlp_kernel<<<(RARE + 127) / 128, 256, SM_TOTAL>>>(srare, cw1t, cb1, cw2t, cb2, cm, RARE);
    // t-MLP over gathered pos_u rows -> g_tu  (64 CTAs)
    mlp_kernel<<<B_SZ / 128, 256, SM_TOTAL>>>(sposu, tw1t, tb1, tw2t, tb2, tu, B_SZ);

    // Scoring + reduction
    score_kernel<<<B_SZ / 8, 256>>>(pos_u, pos_v, neg_v, u_emb, v_emb);
    reduce_kernel<<<1, 1024>>>(out);

    (void)in_sizes; (void)n_in; (void)out_size;
}

// round 4
// speedup vs baseline: 4.6973x; 1.3827x over previous
#include <cuda_runtime.h>
#include <cuda_bf16.h>
#include <cstdint>
#include <cstddef>

// Problem constants
#define V_SZ   100000
#define D_SZ   256
#define S_SZ   128
#define H_SZ   512
#define B_SZ   8192
#define K_SZ   32
#define NREG   60000
#define RARE   40000

// ---------------------------------------------------------------------------
// Scratch (device globals; allocation is forbidden)
// ---------------------------------------------------------------------------
__device__ __nv_bfloat16 g_srare[RARE * S_SZ];        // rare stoich rows, bf16
__device__ __nv_bfloat16 g_sposu[B_SZ * S_SZ];        // gathered pos_u stoich, bf16
__device__ __nv_bfloat16 g_cw1t[H_SZ * S_SZ];         // cw1^T [512x128] (K-major)
__device__ __nv_bfloat16 g_cw2t[D_SZ * H_SZ];         // cw2^T [256x512]
__device__ __nv_bfloat16 g_tw1t[H_SZ * S_SZ];         // tw1^T
__device__ __nv_bfloat16 g_tw2t[D_SZ * H_SZ];         // tw2^T
__device__ float g_cm[RARE * D_SZ];                   // c-MLP table (rare vocab)
__device__ float g_tu[B_SZ * D_SZ];                   // t-MLP per pos_u row
__device__ float g_partial[B_SZ / 8];

// ---------------------------------------------------------------------------
// Helpers
// ---------------------------------------------------------------------------
__device__ __forceinline__ uint32_t smem_u32(const void* p) {
    uint32_t a;
    asm("{ .reg .u64 t; cvta.to.shared.u64 t, %1; cvt.u32.u64 %0, t; }" : "=r"(a) : "l"(p));
    return a;
}
__device__ __forceinline__ void ldsm4(uint32_t& r0, uint32_t& r1, uint32_t& r2, uint32_t& r3,
                                      uint32_t addr) {
    asm volatile("ldmatrix.sync.aligned.m8n8.x4.shared.b16 {%0,%1,%2,%3}, [%4];"
                 : "=r"(r0), "=r"(r1), "=r"(r2), "=r"(r3) : "r"(addr));
}
__device__ __forceinline__ void mma16816(float* c, const uint32_t* a, const uint32_t* b) {
    asm volatile(
        "mma.sync.aligned.m16n8k16.row.col.f32.bf16.bf16.f32 "
        "{%0,%1,%2,%3}, {%4,%5,%6,%7}, {%8,%9}, {%0,%1,%2,%3};"
        : "+f"(c[0]), "+f"(c[1]), "+f"(c[2]), "+f"(c[3])
        : "r"(a[0]), "r"(a[1]), "r"(a[2]), "r"(a[3]), "r"(b[0]), "r"(b[1]));
}
#define CPA16(dst, src) \
    asm volatile("cp.async.cg.shared.global [%0], [%1], 16;" :: "r"(dst), "l"(src))
#define CPA_COMMIT() asm volatile("cp.async.commit_group;" ::: "memory")
#define CPA_WAIT0()  asm volatile("cp.async.wait_group 0;" ::: "memory")

// SMEM layout (bytes, dynamic)
#define SM_A   0            // 128x128 bf16, 256B rows, XOR-swizzled (32KB)
#define SM_W0  32768        // W chunk buffer 0 (32KB)
#define SM_W1  65536        // W chunk buffer 1 (32KB)
#define SM_H   98304        // 128x512 bf16 hidden, 1024B rows (128KB)
#define SM_TOTAL 229376

#define NB_C 313            // c-MLP CTAs (ceil(40000/128))
#define NB_T 64             // t-MLP CTAs (8192/128)

// ---------------------------------------------------------------------------
// Merged fused 2-layer MLP for BOTH branches.
// C[M,256] = relu(A[M,128] @ W1 + b1) @ W2 + b2
// 256 threads = 8 warps (4 M-warps x 2 N-warps); 128 rows per CTA.
// W chunks double-buffered via cp.async.
// ---------------------------------------------------------------------------
__global__ __launch_bounds__(256) void mlp_kernel(
    const float* __restrict__ cB1, const float* __restrict__ cB2,
    const float* __restrict__ tB1, const float* __restrict__ tB2)
{
    extern __shared__ char smem[];
    const uint32_t sb = smem_u32(smem);
    const int tid = threadIdx.x;
    const int lane = tid & 31;
    const int wid = tid >> 5;
    const int mw = wid & 3;
    const int nw = wid >> 2;

    const bool isC = blockIdx.x < NB_C;
    const __nv_bfloat16* A   = isC ? g_srare : g_sposu;
    const __nv_bfloat16* W1t = isC ? g_cw1t : g_tw1t;
    const __nv_bfloat16* W2t = isC ? g_cw2t : g_tw2t;
    const float* b1 = isC ? cB1 : tB1;
    const float* b2 = isC ? cB2 : tB2;
    float* C = isC ? g_cm : g_tu;
    const int M  = isC ? RARE : B_SZ;
    const int m0 = (isC ? blockIdx.x : blockIdx.x - NB_C) * 128;

    // ---- Prologue: async-load A tile + W chunk 0 (one group) ----
    #pragma unroll
    for (int i = 0; i < 8; i++) {
        int c = i * 256 + tid;
        int row = c >> 4, ch = c & 15;
        int rg = m0 + row; if (rg > M - 1) rg = M - 1;
        CPA16(sb + SM_A + row * 256 + ((ch ^ (row & 7)) << 4),
              (const uint4*)A + (size_t)rg * 16 + ch);
    }
    #pragma unroll
    for (int i = 0; i < 8; i++) {
        int c = i * 256 + tid;
        int r = c >> 4, ch = c & 15;
        CPA16(sb + SM_W0 + r * 256 + ((ch ^ (r & 7)) << 4),
              (const uint4*)W1t + (size_t)r * 16 + ch);
    }
    CPA_COMMIT();

    float acc[2][8][4];

    // ---- 12 chunks: 0..3 = layer1 N-chunks, 4..11 = layer2 (nc, kc) ----
    for (int c = 0; c < 12; c++) {
        CPA_WAIT0();
        __syncthreads();

        // Issue next chunk into the other buffer (overlaps with compute below)
        if (c < 11) {
            int n = c + 1;
            uint32_t dst = sb + ((n & 1) ? SM_W1 : SM_W0);
            if (n < 4) {
                #pragma unroll
                for (int i = 0; i < 8; i++) {
                    int q = i * 256 + tid;
                    int r = q >> 4, ch = q & 15;
                    CPA16(dst + r * 256 + ((ch ^ (r & 7)) << 4),
                          (const uint4*)W1t + (size_t)(n * 128 + r) * 16 + ch);
                }
            } else {
                int nc = (n - 4) >> 2, kc = (n - 4) & 3;
                #pragma unroll
                for (int i = 0; i < 8; i++) {
                    int q = i * 256 + tid;
                    int r = q >> 4, ch = q & 15;
                    CPA16(dst + r * 256 + ((ch ^ (r & 7)) << 4),
                          (const uint4*)W2t + (size_t)(nc * 128 + r) * 64 + kc * 16 + ch);
                }
            }
            CPA_COMMIT();
        }

        const uint32_t wbase = sb + ((c & 1) ? SM_W1 : SM_W0);

        if (c < 4) {
            // ================= Layer 1 chunk c =================
            #pragma unroll
            for (int mt = 0; mt < 2; mt++)
                #pragma unroll
                for (int nt = 0; nt < 8; nt++)
                    #pragma unroll
                    for (int q = 0; q < 4; q++) acc[mt][nt][q] = 0.f;

            #pragma unroll
            for (int ks = 0; ks < 8; ks++) {
                uint32_t a[2][4];
                #pragma unroll
                for (int mt = 0; mt < 2; mt++) {
                    int row = mw * 32 + mt * 16 + (lane & 15);
                    int ch  = ks * 2 + (lane >> 4);
                    ldsm4(a[mt][0], a[mt][1], a[mt][2], a[mt][3],
                          sb + SM_A + row * 256 + ((ch ^ (row & 7)) << 4));
                }
                uint32_t b[8][2];
                #pragma unroll
                for (int ntp = 0; ntp < 4; ntp++) {
                    int row = nw * 64 + ntp * 16 + (lane & 7) + ((lane >> 4) << 3);
                    int ch  = ks * 2 + ((lane >> 3) & 1);
                    ldsm4(b[2 * ntp][0], b[2 * ntp][1], b[2 * ntp + 1][0], b[2 * ntp + 1][1],
                          wbase + row * 256 + ((ch ^ (row & 7)) << 4));
                }
                #pragma unroll
                for (int mt = 0; mt < 2; mt++)
                    #pragma unroll
                    for (int nt = 0; nt < 8; nt++)
                        mma16816(acc[mt][nt], a[mt], b[nt]);
            }

            // Epilogue: bias + relu -> bf16 hidden in SMEM
            #pragma unroll
            for (int mt = 0; mt < 2; mt++)
                #pragma unroll
                for (int nt = 0; nt < 8; nt++) {
                    int nloc = nw * 64 + nt * 8 + 2 * (lane & 3);
                    int ng = c * 128 + nloc;
                    float2 bb = *(const float2*)(b1 + ng);
                    float h0 = fmaxf(acc[mt][nt][0] + bb.x, 0.f);
                    float h1 = fmaxf(acc[mt][nt][1] + bb.y, 0.f);
                    float h2 = fmaxf(acc[mt][nt][2] + bb.x, 0.f);
                    float h3 = fmaxf(acc[mt][nt][3] + bb.y, 0.f);
                    __nv_bfloat162 p0 = __float22bfloat162_rn(make_float2(h0, h1));
                    __nv_bfloat162 p1 = __float22bfloat162_rn(make_float2(h2, h3));
                    int ch = ng >> 3, w = (ng & 7) * 2;
                    int r0 = mw * 32 + mt * 16 + (lane >> 2);
                    int r1 = r0 + 8;
                    *(unsigned*)(smem + SM_H + r0 * 1024 + ((ch ^ (r0 & 7)) << 4) + w) =
                        *(unsigned*)&p0;
                    *(unsigned*)(smem + SM_H + r1 * 1024 + ((ch ^ (r1 & 7)) << 4) + w) =
                        *(unsigned*)&p1;
                }
        } else {
            // ================= Layer 2 chunk (nc, kc) =================
            const int nc = (c - 4) >> 2, kc = (c - 4) & 3;
            if (kc == 0) {
                #pragma unroll
                for (int mt = 0; mt < 2; mt++)
                    #pragma unroll
                    for (int nt = 0; nt < 8; nt++)
                        #pragma unroll
                        for (int q = 0; q < 4; q++) acc[mt][nt][q] = 0.f;
            }

            #pragma unroll
            for (int ks = 0; ks < 8; ks++) {
                uint32_t a[2][4];
                #pragma unroll
                for (int mt = 0; mt < 2; mt++) {
                    int row = mw * 32 + mt * 16 + (lane & 15);
                    int ch  = kc * 16 + ks * 2 + (lane >> 4);
                    ldsm4(a[mt][0], a[mt][1], a[mt][2], a[mt][3],
                          sb + SM_H + row * 1024 + ((ch ^ (row & 7)) << 4));
                }
                uint32_t b[8][2];
                #pragma unroll
                for (int ntp = 0; ntp < 4; ntp++) {
                    int row = nw * 64 + ntp * 16 + (lane & 7) + ((lane >> 4) << 3);
                    int ch  = ks * 2 + ((lane >> 3) & 1);
                    ldsm4(b[2 * ntp][0], b[2 * ntp][1], b[2 * ntp + 1][0], b[2 * ntp + 1][1],
                          wbase + row * 256 + ((ch ^ (row & 7)) << 4));
                }
                #pragma unroll
                for (int mt = 0; mt < 2; mt++)
                    #pragma unroll
                    for (int nt = 0; nt < 8; nt++)
                        mma16816(acc[mt][nt], a[mt], b[nt]);
            }

            if (kc == 3) {
                // Epilogue: + bias -> fp32 global
                #pragma unroll
                for (int mt = 0; mt < 2; mt++)
                    #pragma unroll
                    for (int nt = 0; nt < 8; nt++) {
                        int ng = nc * 128 + nw * 64 + nt * 8 + 2 * (lane & 3);
                        float2 bb = *(const float2*)(b2 + ng);
                        int r0 = m0 + mw * 32 + mt * 16 + (lane >> 2);
                        int r1 = r0 + 8;
                        if (r0 < M) {
                            float2 o = make_float2(acc[mt][nt][0] + bb.x,
                                                   acc[mt][nt][1] + bb.y);
                            *(float2*)(C + (size_t)r0 * D_SZ + ng) = o;
                        }
                        if (r1 < M) {
                            float2 o = make_float2(acc[mt][nt][2] + bb.x,
                                                   acc[mt][nt][3] + bb.y);
                            *(float2*)(C + (size_t)r1 * D_SZ + ng) = o;
                        }
                    }
            }
        }
    }
}

// ---------------------------------------------------------------------------
// Fused prep: conv rare stoich | gather pos_u | 4x coalesced weight transpose
// Block ranges: [0,5000) conv, [5000,6024) gather,
//               [6024,6088) cw1, [6088,6152) tw1, [6152,6280) cw2, [6280,6408) tw2
// ---------------------------------------------------------------------------
__global__ __launch_bounds__(256) void prep_kernel(
    const float* __restrict__ stoich, const int* __restrict__ pos_u,
    const float* __restrict__ cw1, const float* __restrict__ cw2,
    const float* __restrict__ tw1, const float* __restrict__ tw2)
{
    const int bx = blockIdx.x;
    const int tid = threadIdx.x;

    if (bx < 5000) {                        // conv rare stoich -> bf16
        int t = bx * 256 + tid;
        float4 f = ((const float4*)(stoich + (size_t)NREG * S_SZ))[t];
        __nv_bfloat162 h0 = __float22bfloat162_rn(make_float2(f.x, f.y));
        __nv_bfloat162 h1 = __float22bfloat162_rn(make_float2(f.z, f.w));
        uint2 u; u.x = *(unsigned*)&h0; u.y = *(unsigned*)&h1;
        ((uint2*)g_srare)[t] = u;
        return;
    }
    if (bx < 6024) {                        // gather pos_u stoich -> bf16
        int t = (bx - 5000) * 256 + tid;
        int row = t >> 5, c4 = t & 31;
        int r = pos_u[row];
        float4 f = ((const float4*)(stoich + (size_t)r * S_SZ))[c4];
        __nv_bfloat162 h0 = __float22bfloat162_rn(make_float2(f.x, f.y));
        __nv_bfloat162 h1 = __float22bfloat162_rn(make_float2(f.z, f.w));
        uint2 u; u.x = *(unsigned*)&h0; u.y = *(unsigned*)&h1;
        ((uint2*)g_sposu)[(size_t)row * 32 + c4] = u;
        return;
    }

    // Tiled transpose: w [K x N] fp32 -> wt [N x K] bf16
    __shared__ float tile[32][33];
    const float* w; __nv_bfloat16* wt; int K, N, tt;
    if (bx < 6088)      { w = cw1; wt = g_cw1t; K = S_SZ; N = H_SZ; tt = bx - 6024; }
    else if (bx < 6152) { w = tw1; wt = g_tw1t; K = S_SZ; N = H_SZ; tt = bx - 6088; }
    else if (bx < 6280) { w = cw2; wt = g_cw2t; K = H_SZ; N = D_SZ; tt = bx - 6152; }
    else                { w = tw2; wt = g_tw2t; K = H_SZ; N = D_SZ; tt = bx - 6280; }

    const int Kt = K >> 5;
    const int kt = tt % Kt, nt = tt / Kt;
    const int cc = tid & 31, rr = tid >> 5;   // 32 x 8 threads
    #pragma unroll
    for (int j = 0; j < 4; j++) {
        int row = rr + j * 8;
        tile[row][cc] = w[(size_t)(kt * 32 + row) * N + nt * 32 + cc];
    }
    __syncthreads();
    #pragma unroll
    for (int j = 0; j < 4; j++) {
        int row = rr + j * 8;
        wt[(size_t)(nt * 32 + row) * K + kt * 32 + cc] = __float2bfloat16(tile[cc][row]);
    }
}

// ---------------------------------------------------------------------------
// Scoring (fp32): one warp per pair.
// total_b = 2*( -logsig(clip(EU.EV)) + sum_k -logsig(-clip(EU.ENVk)) )
// ---------------------------------------------------------------------------
__device__ __forceinline__ float clip10(float x) { return fminf(fmaxf(x, -10.f), 10.f); }
__device__ __forceinline__ float warp_reduce(float v) {
    #pragma unroll
    for (int s = 16; s > 0; s >>= 1) v += __shfl_xor_sync(0xffffffffu, v, s);
    return v;
}

__global__ __launch_bounds__(256) void score_kernel(
    const int* __restrict__ pos_u, const int* __restrict__ pos_v,
    const int* __restrict__ neg_v,
    const float* __restrict__ u_emb, const float* __restrict__ v_emb)
{
    __shared__ float bsum[8];
    const int warp = threadIdx.x >> 5;
    const int lane = threadIdx.x & 31;
    const int b = blockIdx.x * 8 + warp;

    const int pu = pos_u[b];
    const int pv = pos_v[b];

    const float4* eup = (const float4*)(pu < NREG ? u_emb + (size_t)pu * D_SZ
                                                  : g_tu + (size_t)b * D_SZ);
    const float4* evp = (const float4*)(pv < NREG ? v_emb + (size_t)pv * D_SZ
                                                  : g_cm + (size_t)(pv - NREG) * D_SZ);
    const float4 e0 = eup[lane * 2 + 0];
    const float4 e1 = eup[lane * 2 + 1];
    const float4 v0 = evp[lane * 2 + 0];
    const float4 v1 = evp[lane * 2 + 1];

    float d = e0.x * v0.x + e0.y * v0.y + e0.z * v0.z + e0.w * v0.w
            + e1.x * v1.x + e1.y * v1.y + e1.z * v1.z + e1.w * v1.w;
    d = warp_reduce(d);
    float x = clip10(d);
    float s = log1pf(expf(-fabsf(x))) - fminf(x, 0.f);

    const int mynv = neg_v[(size_t)b * K_SZ + lane];
    #pragma unroll 4
    for (int k = 0; k < K_SZ; k++) {
        int nv = __shfl_sync(0xffffffffu, mynv, k);
        const float4* np = (const float4*)(nv < NREG ? v_emb + (size_t)nv * D_SZ
                                                     : g_cm + (size_t)(nv - NREG) * D_SZ);
        float4 n0 = np[lane * 2 + 0];
        float4 n1 = np[lane * 2 + 1];
        float dn = e0.x * n0.x + e0.y * n0.y + e0.z * n0.z + e0.w * n0.w
                 + e1.x * n1.x + e1.y * n1.y + e1.z * n1.z + e1.w * n1.w;
        dn = warp_reduce(dn);
        float xn = clip10(dn);
        s += fmaxf(xn, 0.f) + log1pf(expf(-fabsf(xn)));
    }

    if (lane == 0) bsum[warp] = 2.f * s;
    __syncthreads();
    if (threadIdx.x == 0) {
        float t = 0.f;
        #pragma unroll
        for (int i = 0; i < 8; i++) t += bsum[i];
        g_partial[blockIdx.x] = t;
    }
}

__global__ __launch_bounds__(1024) void reduce_kernel(float* __restrict__ out) {
    __shared__ float s[1024];
    const int t = threadIdx.x;
    s[t] = g_partial[t];
    __syncthreads();
    #pragma unroll
    for (int st = 512; st > 0; st >>= 1) {
        if (t < st) s[t] += s[t + st];
        __syncthreads();
    }
    if (t == 0) out[0] = s[0] / (float)B_SZ;
}

// ---------------------------------------------------------------------------
// Launch
// ---------------------------------------------------------------------------
extern "C" void kernel_launch(void* const* d_in, const int* in_sizes, int n_in,
                              void* d_out, int out_size)
{
    const int*   pos_u  = (const int*)  d_in[0];
    const int*   pos_v  = (const int*)  d_in[1];
    const int*   neg_v  = (const int*)  d_in[2];
    const float* u_emb  = (const float*)d_in[3];
    const float* v_emb  = (const float*)d_in[4];
    const float* stoich = (const float*)d_in[5];
    const float* tw1    = (const float*)d_in[6];
    const float* tb1    = (const float*)d_in[7];
    const float* tw2    = (const float*)d_in[8];
    const float* tb2    = (const float*)d_in[9];
    const float* cw1    = (const float*)d_in[10];
    const float* cb1    = (const float*)d_in[11];
    const float* cw2    = (const float*)d_in[12];
    const float* cb2    = (const float*)d_in[13];
    float* out = (float*)d_out;

    static bool attr_set = false;
    if (!attr_set) {
        cudaFuncSetAttribute(mlp_kernel, cudaFuncAttributeMaxDynamicSharedMemorySize, SM_TOTAL);
        attr_set = true;
    }

    // 1) fused prep: bf16 conversions, gather, coalesced weight transposes
    prep_kernel<<<6408, 256>>>(stoich, pos_u, cw1, cw2, tw1, tw2);
    // 2) merged c+t fused two-layer MLP (313 + 64 CTAs)
    mlp_kernel<<<NB_C + NB_T, 256, SM_TOTAL>>>(cb1, cb2, tb1, tb2);
    // 3) scoring + reduction
    score_kernel<<<B_SZ / 8, 256>>>(pos_u, pos_v, neg_v, u_emb, v_emb);
    reduce_kernel<<<1, 1024>>>(out);

    (void)in_sizes; (void)n_in; (void)out_size;
}

// round 5
// speedup vs baseline: 4.8895x; 1.0409x over previous
#include <cuda_runtime.h>
#include <cuda_bf16.h>
#include <cstdint>
#include <cstddef>

// Problem constants
#define V_SZ   100000
#define D_SZ   256
#define S_SZ   128
#define H_SZ   512
#define B_SZ   8192
#define K_SZ   32
#define NREG   60000
#define RARE   40000

// ---------------------------------------------------------------------------
// Scratch (device globals; allocation is forbidden)
// ---------------------------------------------------------------------------
__device__ __nv_bfloat16 g_cw1t[H_SZ * S_SZ];         // cw1^T [512x128] (K-major)
__device__ __nv_bfloat16 g_cw2t[D_SZ * H_SZ];         // cw2^T [256x512]
__device__ __nv_bfloat16 g_tw1t[H_SZ * S_SZ];         // tw1^T
__device__ __nv_bfloat16 g_tw2t[D_SZ * H_SZ];         // tw2^T
__device__ float g_cm[RARE * D_SZ];                   // c-MLP table (rare vocab)
__device__ float g_tu[B_SZ * D_SZ];                   // t-MLP per pos_u row
__device__ float g_partial[B_SZ / 8];                 // 1024 block partials
__device__ unsigned g_ticket;                         // self-resetting (wraps)

// ---------------------------------------------------------------------------
// Helpers
// ---------------------------------------------------------------------------
__device__ __forceinline__ uint32_t smem_u32(const void* p) {
    uint32_t a;
    asm("{ .reg .u64 t; cvta.to.shared.u64 t, %1; cvt.u32.u64 %0, t; }" : "=r"(a) : "l"(p));
    return a;
}
__device__ __forceinline__ void ldsm4(uint32_t& r0, uint32_t& r1, uint32_t& r2, uint32_t& r3,
                                      uint32_t addr) {
    asm volatile("ldmatrix.sync.aligned.m8n8.x4.shared.b16 {%0,%1,%2,%3}, [%4];"
                 : "=r"(r0), "=r"(r1), "=r"(r2), "=r"(r3) : "r"(addr));
}
__device__ __forceinline__ void mma16816(float* c, const uint32_t* a, const uint32_t* b) {
    asm volatile(
        "mma.sync.aligned.m16n8k16.row.col.f32.bf16.bf16.f32 "
        "{%0,%1,%2,%3}, {%4,%5,%6,%7}, {%8,%9}, {%0,%1,%2,%3};"
        : "+f"(c[0]), "+f"(c[1]), "+f"(c[2]), "+f"(c[3])
        : "r"(a[0]), "r"(a[1]), "r"(a[2]), "r"(a[3]), "r"(b[0]), "r"(b[1]));
}
#define CPA16(dst, src) \
    asm volatile("cp.async.cg.shared.global [%0], [%1], 16;" :: "r"(dst), "l"(src))
#define CPA_COMMIT() asm volatile("cp.async.commit_group;" ::: "memory")
#define CPA_WAIT0()  asm volatile("cp.async.wait_group 0;" ::: "memory")

// SMEM layout (bytes, dynamic)
#define SM_A   0            // 128x128 bf16, 256B rows, XOR-swizzled (32KB)
#define SM_W0  32768        // W chunk buffer 0 (32KB)
#define SM_W1  65536        // W chunk buffer 1 (32KB)
#define SM_H   98304        // 128x512 bf16 hidden, 1024B rows (128KB)
#define SM_TOTAL 229376

#define NB_C 313            // c-MLP CTAs (ceil(40000/128))
#define NB_T 64             // t-MLP CTAs (8192/128)

// ---------------------------------------------------------------------------
// Merged fused 2-layer MLP for BOTH branches.
// C[M,256] = relu(A[M,128] @ W1 + b1) @ W2 + b2
// A gathered DIRECTLY from fp32 stoich (seq rows for c, pos_u rows for t),
// converted to bf16 in the prologue. W chunks double-buffered via cp.async.
// 256 threads = 8 warps (4 M-warps x 2 N-warps); 128 rows per CTA.
// ---------------------------------------------------------------------------
__global__ __launch_bounds__(256) void mlp_kernel(
    const float* __restrict__ stoich, const int* __restrict__ pos_u,
    const float* __restrict__ cB1, const float* __restrict__ cB2,
    const float* __restrict__ tB1, const float* __restrict__ tB2)
{
    extern __shared__ char smem[];
    const uint32_t sb = smem_u32(smem);
    const int tid = threadIdx.x;
    const int lane = tid & 31;
    const int wid = tid >> 5;
    const int mw = wid & 3;
    const int nw = wid >> 2;

    const bool isC = blockIdx.x < NB_C;
    const __nv_bfloat16* W1t = isC ? g_cw1t : g_tw1t;
    const __nv_bfloat16* W2t = isC ? g_cw2t : g_tw2t;
    const float* b1 = isC ? cB1 : tB1;
    const float* b2 = isC ? cB2 : tB2;
    float* C = isC ? g_cm : g_tu;
    const int M  = isC ? RARE : B_SZ;
    const int m0 = (isC ? blockIdx.x : blockIdx.x - NB_C) * 128;

    // ---- Prologue: async-load W chunk 0 ----
    #pragma unroll
    for (int i = 0; i < 8; i++) {
        int c = i * 256 + tid;
        int r = c >> 4, ch = c & 15;
        CPA16(sb + SM_W0 + r * 256 + ((ch ^ (r & 7)) << 4),
              (const uint4*)W1t + (size_t)r * 16 + ch);
    }
    CPA_COMMIT();

    // ---- Gather A rows from fp32 stoich, convert to bf16, swizzled store ----
    #pragma unroll
    for (int i = 0; i < 16; i++) {
        int idx = i * 256 + tid;             // 4096 float4 chunks (128 rows x 32)
        int row = idx >> 5, c4 = idx & 31;
        int rl = m0 + row; if (rl > M - 1) rl = M - 1;
        int rg = isC ? (NREG + rl) : pos_u[rl];
        float4 f = ((const float4*)stoich)[(size_t)rg * 32 + c4];
        __nv_bfloat162 p0 = __float22bfloat162_rn(make_float2(f.x, f.y));
        __nv_bfloat162 p1 = __float22bfloat162_rn(make_float2(f.z, f.w));
        uint2 u; u.x = *(unsigned*)&p0; u.y = *(unsigned*)&p1;
        int ch = c4 >> 1;
        *(uint2*)(smem + SM_A + row * 256 + ((ch ^ (row & 7)) << 4) + (c4 & 1) * 8) = u;
    }

    float acc[2][8][4];

    // ---- 12 chunks: 0..3 = layer1 N-chunks, 4..11 = layer2 (nc, kc) ----
    for (int c = 0; c < 12; c++) {
        CPA_WAIT0();
        __syncthreads();

        // Issue next chunk into the other buffer (overlaps with compute below)
        if (c < 11) {
            int n = c + 1;
            uint32_t dst = sb + ((n & 1) ? SM_W1 : SM_W0);
            if (n < 4) {
                #pragma unroll
                for (int i = 0; i < 8; i++) {
                    int q = i * 256 + tid;
                    int r = q >> 4, ch = q & 15;
                    CPA16(dst + r * 256 + ((ch ^ (r & 7)) << 4),
                          (const uint4*)W1t + (size_t)(n * 128 + r) * 16 + ch);
                }
            } else {
                int nc = (n - 4) >> 2, kc = (n - 4) & 3;
                #pragma unroll
                for (int i = 0; i < 8; i++) {
                    int q = i * 256 + tid;
                    int r = q >> 4, ch = q & 15;
                    CPA16(dst + r * 256 + ((ch ^ (r & 7)) << 4),
                          (const uint4*)W2t + (size_t)(nc * 128 + r) * 64 + kc * 16 + ch);
                }
            }
            CPA_COMMIT();
        }

        const uint32_t wbase = sb + ((c & 1) ? SM_W1 : SM_W0);

        if (c < 4) {
            // ================= Layer 1 chunk c =================
            #pragma unroll
            for (int mt = 0; mt < 2; mt++)
                #pragma unroll
                for (int nt = 0; nt < 8; nt++)
                    #pragma unroll
                    for (int q = 0; q < 4; q++) acc[mt][nt][q] = 0.f;

            #pragma unroll
            for (int ks = 0; ks < 8; ks++) {
                uint32_t a[2][4];
                #pragma unroll
                for (int mt = 0; mt < 2; mt++) {
                    int row = mw * 32 + mt * 16 + (lane & 15);
                    int ch  = ks * 2 + (lane >> 4);
                    ldsm4(a[mt][0], a[mt][1], a[mt][2], a[mt][3],
                          sb + SM_A + row * 256 + ((ch ^ (row & 7)) << 4));
                }
                uint32_t b[8][2];
                #pragma unroll
                for (int ntp = 0; ntp < 4; ntp++) {
                    int row = nw * 64 + ntp * 16 + (lane & 7) + ((lane >> 4) << 3);
                    int ch  = ks * 2 + ((lane >> 3) & 1);
                    ldsm4(b[2 * ntp][0], b[2 * ntp][1], b[2 * ntp + 1][0], b[2 * ntp + 1][1],
                          wbase + row * 256 + ((ch ^ (row & 7)) << 4));
                }
                #pragma unroll
                for (int mt = 0; mt < 2; mt++)
                    #pragma unroll
                    for (int nt = 0; nt < 8; nt++)
                        mma16816(acc[mt][nt], a[mt], b[nt]);
            }

            // Epilogue: bias + relu -> bf16 hidden in SMEM
            #pragma unroll
            for (int mt = 0; mt < 2; mt++)
                #pragma unroll
                for (int nt = 0; nt < 8; nt++) {
                    int nloc = nw * 64 + nt * 8 + 2 * (lane & 3);
                    int ng = c * 128 + nloc;
                    float2 bb = *(const float2*)(b1 + ng);
                    float h0 = fmaxf(acc[mt][nt][0] + bb.x, 0.f);
                    float h1 = fmaxf(acc[mt][nt][1] + bb.y, 0.f);
                    float h2 = fmaxf(acc[mt][nt][2] + bb.x, 0.f);
                    float h3 = fmaxf(acc[mt][nt][3] + bb.y, 0.f);
                    __nv_bfloat162 p0 = __float22bfloat162_rn(make_float2(h0, h1));
                    __nv_bfloat162 p1 = __float22bfloat162_rn(make_float2(h2, h3));
                    int ch = ng >> 3, w = (ng & 7) * 2;
                    int r0 = mw * 32 + mt * 16 + (lane >> 2);
                    int r1 = r0 + 8;
                    *(unsigned*)(smem + SM_H + r0 * 1024 + ((ch ^ (r0 & 7)) << 4) + w) =
                        *(unsigned*)&p0;
                    *(unsigned*)(smem + SM_H + r1 * 1024 + ((ch ^ (r1 & 7)) << 4) + w) =
                        *(unsigned*)&p1;
                }
        } else {
            // ================= Layer 2 chunk (nc, kc) =================
            const int nc = (c - 4) >> 2, kc = (c - 4) & 3;
            if (kc == 0) {
                #pragma unroll
                for (int mt = 0; mt < 2; mt++)
                    #pragma unroll
                    for (int nt = 0; nt < 8; nt++)
                        #pragma unroll
                        for (int q = 0; q < 4; q++) acc[mt][nt][q] = 0.f;
            }

            #pragma unroll
            for (int ks = 0; ks < 8; ks++) {
                uint32_t a[2][4];
                #pragma unroll
                for (int mt = 0; mt < 2; mt++) {
                    int row = mw * 32 + mt * 16 + (lane & 15);
                    int ch  = kc * 16 + ks * 2 + (lane >> 4);
                    ldsm4(a[mt][0], a[mt][1], a[mt][2], a[mt][3],
                          sb + SM_H + row * 1024 + ((ch ^ (row & 7)) << 4));
                }
                uint32_t b[8][2];
                #pragma unroll
                for (int ntp = 0; ntp < 4; ntp++) {
                    int row = nw * 64 + ntp * 16 + (lane & 7) + ((lane >> 4) << 3);
                    int ch  = ks * 2 + ((lane >> 3) & 1);
                    ldsm4(b[2 * ntp][0], b[2 * ntp][1], b[2 * ntp + 1][0], b[2 * ntp + 1][1],
                          wbase + row * 256 + ((ch ^ (row & 7)) << 4));
                }
                #pragma unroll
                for (int mt = 0; mt < 2; mt++)
                    #pragma unroll
                    for (int nt = 0; nt < 8; nt++)
                        mma16816(acc[mt][nt], a[mt], b[nt]);
            }

            if (kc == 3) {
                // Epilogue: + bias -> fp32 global
                #pragma unroll
                for (int mt = 0; mt < 2; mt++)
                    #pragma unroll
                    for (int nt = 0; nt < 8; nt++) {
                        int ng = nc * 128 + nw * 64 + nt * 8 + 2 * (lane & 3);
                        float2 bb = *(const float2*)(b2 + ng);
                        int r0 = m0 + mw * 32 + mt * 16 + (lane >> 2);
                        int r1 = r0 + 8;
                        if (r0 < M) {
                            float2 o = make_float2(acc[mt][nt][0] + bb.x,
                                                   acc[mt][nt][1] + bb.y);
                            *(float2*)(C + (size_t)r0 * D_SZ + ng) = o;
                        }
                        if (r1 < M) {
                            float2 o = make_float2(acc[mt][nt][2] + bb.x,
                                                   acc[mt][nt][3] + bb.y);
                            *(float2*)(C + (size_t)r1 * D_SZ + ng) = o;
                        }
                    }
            }
        }
    }
}

// ---------------------------------------------------------------------------
// Prep: 4x coalesced weight transpose (fp32 [K x N] -> bf16 [N x K])
// Blocks: [0,64) cw1, [64,128) tw1, [128,256) cw2, [256,384) tw2
// ---------------------------------------------------------------------------
__global__ __launch_bounds__(256) void prep_kernel(
    const float* __restrict__ cw1, const float* __restrict__ cw2,
    const float* __restrict__ tw1, const float* __restrict__ tw2)
{
    const int bx = blockIdx.x;
    const int tid = threadIdx.x;

    __shared__ float tile[32][33];
    const float* w; __nv_bfloat16* wt; int K, N, tt;
    if (bx < 64)       { w = cw1; wt = g_cw1t; K = S_SZ; N = H_SZ; tt = bx; }
    else if (bx < 128) { w = tw1; wt = g_tw1t; K = S_SZ; N = H_SZ; tt = bx - 64; }
    else if (bx < 256) { w = cw2; wt = g_cw2t; K = H_SZ; N = D_SZ; tt = bx - 128; }
    else               { w = tw2; wt = g_tw2t; K = H_SZ; N = D_SZ; tt = bx - 256; }

    const int Kt = K >> 5;
    const int kt = tt % Kt, nt = tt / Kt;
    const int cc = tid & 31, rr = tid >> 5;   // 32 x 8 threads
    #pragma unroll
    for (int j = 0; j < 4; j++) {
        int row = rr + j * 8;
        tile[row][cc] = w[(size_t)(kt * 32 + row) * N + nt * 32 + cc];
    }
    __syncthreads();
    #pragma unroll
    for (int j = 0; j < 4; j++) {
        int row = rr + j * 8;
        wt[(size_t)(nt * 32 + row) * K + kt * 32 + cc] = __float2bfloat16(tile[cc][row]);
    }
}

// ---------------------------------------------------------------------------
// Scoring (fp32) + fused final reduction: one warp per pair.
// total_b = 2*( -logsig(clip(EU.EV)) + sum_k -logsig(-clip(EU.ENVk)) )
// Last-arriving block (self-resetting atomicInc ticket) reduces all partials.
// ---------------------------------------------------------------------------
__device__ __forceinline__ float clip10(float x) { return fminf(fmaxf(x, -10.f), 10.f); }
__device__ __forceinline__ float warp_reduce(float v) {
    #pragma unroll
    for (int s = 16; s > 0; s >>= 1) v += __shfl_xor_sync(0xffffffffu, v, s);
    return v;
}

__global__ __launch_bounds__(256) void score_kernel(
    const int* __restrict__ pos_u, const int* __restrict__ pos_v,
    const int* __restrict__ neg_v,
    const float* __restrict__ u_emb, const float* __restrict__ v_emb,
    float* __restrict__ out)
{
    __shared__ float bsum[8];
    __shared__ int lastflag;
    const int warp = threadIdx.x >> 5;
    const int lane = threadIdx.x & 31;
    const int b = blockIdx.x * 8 + warp;

    const int pu = pos_u[b];
    const int pv = pos_v[b];

    const float4* eup = (const float4*)(pu < NREG ? u_emb + (size_t)pu * D_SZ
                                                  : g_tu + (size_t)b * D_SZ);
    const float4* evp = (const float4*)(pv < NREG ? v_emb + (size_t)pv * D_SZ
                                                  : g_cm + (size_t)(pv - NREG) * D_SZ);
    const float4 e0 = eup[lane * 2 + 0];
    const float4 e1 = eup[lane * 2 + 1];
    const float4 v0 = evp[lane * 2 + 0];
    const float4 v1 = evp[lane * 2 + 1];

    float d = e0.x * v0.x + e0.y * v0.y + e0.z * v0.z + e0.w * v0.w
            + e1.x * v1.x + e1.y * v1.y + e1.z * v1.z + e1.w * v1.w;
    d = warp_reduce(d);
    float x = clip10(d);
    float s = log1pf(expf(-fabsf(x))) - fminf(x, 0.f);

    const int mynv = neg_v[(size_t)b * K_SZ + lane];
    #pragma unroll 4
    for (int k = 0; k < K_SZ; k++) {
        int nv = __shfl_sync(0xffffffffu, mynv, k);
        const float4* np = (const float4*)(nv < NREG ? v_emb + (size_t)nv * D_SZ
                                                     : g_cm + (size_t)(nv - NREG) * D_SZ);
        float4 n0 = np[lane * 2 + 0];
        float4 n1 = np[lane * 2 + 1];
        float dn = e0.x * n0.x + e0.y * n0.y + e0.z * n0.z + e0.w * n0.w
                 + e1.x * n1.x + e1.y * n1.y + e1.z * n1.z + e1.w * n1.w;
        dn = warp_reduce(dn);
        float xn = clip10(dn);
        s += fmaxf(xn, 0.f) + log1pf(expf(-fabsf(xn)));
    }

    if (lane == 0) bsum[warp] = 2.f * s;
    __syncthreads();
    if (threadIdx.x == 0) {
        float t = 0.f;
        #pragma unroll
        for (int i = 0; i < 8; i++) t += bsum[i];
        g_partial[blockIdx.x] = t;
        __threadfence();
        unsigned old = atomicInc(&g_ticket, gridDim.x - 1);  // wraps to 0 -> replay-safe
        lastflag = (old == gridDim.x - 1);
    }
    __syncthreads();

    if (lastflag) {
        __threadfence();                     // acquire: see all partials
        __shared__ float red[256];
        float v = 0.f;
        #pragma unroll
        for (int j = 0; j < 4; j++)
            v += __ldcg(&g_partial[threadIdx.x * 4 + j]);    // fixed order
        red[threadIdx.x] = v;
        __syncthreads();
        #pragma unroll
        for (int st = 128; st > 0; st >>= 1) {
            if (threadIdx.x < st) red[threadIdx.x] += red[threadIdx.x + st];
            __syncthreads();
        }
        if (threadIdx.x == 0) out[0] = red[0] / (float)B_SZ;
    }
}

// ---------------------------------------------------------------------------
// Launch
// ---------------------------------------------------------------------------
extern "C" void kernel_launch(void* const* d_in, const int* in_sizes, int n_in,
                              void* d_out, int out_size)
{
    const int*   pos_u  = (const int*)  d_in[0];
    const int*   pos_v  = (const int*)  d_in[1];
    const int*   neg_v  = (const int*)  d_in[2];
    const float* u_emb  = (const float*)d_in[3];
    const float* v_emb  = (const float*)d_in[4];
    const float* stoich = (const float*)d_in[5];
    const float* tb1    = (const float*)d_in[7];
    const float* tw2    = (const float*)d_in[8];
    const float* tb2    = (const float*)d_in[9];
    const float* tw1    = (const float*)d_in[6];
    const float* cw1    = (const float*)d_in[10];
    const float* cb1    = (const float*)d_in[11];
    const float* cw2    = (const float*)d_in[12];
    const float* cb2    = (const float*)d_in[13];
    float* out = (float*)d_out;

    static bool attr_set = false;
    if (!attr_set) {
        cudaFuncSetAttribute(mlp_kernel, cudaFuncAttributeMaxDynamicSharedMemorySize, SM_TOTAL);
        attr_set = true;
    }

    // 1) weight transposes (fp32 -> bf16 K-major)
    prep_kernel<<<384, 256>>>(cw1, cw2, tw1, tw2);
    // 2) merged c+t fused two-layer MLP (313 + 64 CTAs), A gathered in-kernel
    mlp_kernel<<<NB_C + NB_T, 256, SM_TOTAL>>>(stoich, pos_u, cb1, cb2, tb1, tb2);
    // 3) scoring + fused final reduction
    score_kernel<<<B_SZ / 8, 256>>>(pos_u, pos_v, neg_v, u_emb, v_emb, out);

    (void)in_sizes; (void)n_in; (void)out_size;
}